// round 2
// baseline (speedup 1.0000x reference)
#include <cuda_runtime.h>
#include <mma.h>

using namespace nvcuda;

namespace {
constexpr int B  = 4;
constexpr int H  = 16;
constexpr int S  = 1024;
constexpr int D  = 1024;
constexpr int DK = 64;
constexpr int DV = 64;
constexpr int HB = H * B;
constexpr float INV_SCALE = 1.0f / 32.0f;        // 1/sqrt(D)
constexpr size_t OUT_ELEMS = (size_t)B * S * D;

// fused attention tiling
constexpr int QT = 32;     // q rows per block
constexpr int CK = 128;    // key/value chunk
constexpr int SC_LD = 1040;
constexpr int KV_LD = 68;
constexpr int QS_LD = 68;
constexpr int SMEM_SC = QT * SC_LD;             // 33280 floats
constexpr int SMEM_KV = CK * KV_LD;             // 8704
constexpr int SMEM_QS = QT * QS_LD;             // 2176
constexpr size_t FUSED_SMEM_BYTES = (size_t)(SMEM_SC + SMEM_KV + SMEM_QS) * 4; // 176640
}

// Scratch (allocation-free rule: __device__ globals)
__device__ float g_q[(size_t)B * S * H * DK];    // [b*S+s][h*64+k]
__device__ float g_k[(size_t)B * S * H * DK];
__device__ float g_v[(size_t)B * S * H * DV];
__device__ float g_ctx[(size_t)B * S * H * DV];  // [b*S+q][h*64+v]

using FragA  = wmma::fragment<wmma::matrix_a, 16, 16, 8, wmma::precision::tf32, wmma::row_major>;
using FragBr = wmma::fragment<wmma::matrix_b, 16, 16, 8, wmma::precision::tf32, wmma::row_major>;
using FragBc = wmma::fragment<wmma::matrix_b, 16, 16, 8, wmma::precision::tf32, wmma::col_major>;
using FragC  = wmma::fragment<wmma::accumulator, 16, 16, 8, float>;

__device__ __forceinline__ float4 tf32x4(float4 v) {
    v.x = wmma::__float_to_tf32(v.x); v.y = wmma::__float_to_tf32(v.y);
    v.z = wmma::__float_to_tf32(v.z); v.w = wmma::__float_to_tf32(v.w);
    return v;
}

// ---------------------------------------------------------------------------
// Kernel 1: QKV projections as 3 full GEMMs with heads concatenated on N.
// C[m][h*64+k] = sum_d X[m][d] * W[h][d][k],  M=4096, N=1024, K=1024
// grid (M/128, N/128, 3), block 256. Block tile 128x128, warp tile 64x32.
// ---------------------------------------------------------------------------
__global__ void __launch_bounds__(256)
proj_kernel(const float* __restrict__ xq, const float* __restrict__ xk,
            const float* __restrict__ xv, const float* __restrict__ wq,
            const float* __restrict__ wk, const float* __restrict__ wv)
{
    const int which = blockIdx.z;
    const float* A = (which == 0) ? xq : (which == 1) ? xk : xv;
    const float* W = (which == 0) ? wq : (which == 1) ? wk : wv;
    float* C       = (which == 0) ? g_q : (which == 1) ? g_k : g_v;

    const int m0 = blockIdx.x * 128;
    const int n0 = blockIdx.y * 128;

    __shared__ float As[128][36];
    __shared__ float Bs[32][132];

    const int tid = threadIdx.x;
    const int warp = tid >> 5;
    const int wm = warp & 1;      // 0..1 -> 64 rows
    const int wn = warp >> 1;     // 0..3 -> 32 cols

    FragC acc[4][2];
#pragma unroll
    for (int i = 0; i < 4; i++) { wmma::fill_fragment(acc[i][0], 0.0f); wmma::fill_fragment(acc[i][1], 0.0f); }

    for (int k0 = 0; k0 < D; k0 += 32) {
#pragma unroll
        for (int i = 0; i < 4; i++) {       // A tile 128x32
            int lin = tid + i * 256;
            int r = lin >> 3, c = (lin & 7) * 4;
            *(float4*)&As[r][c] = tf32x4(*(const float4*)(A + (size_t)(m0 + r) * D + k0 + c));
        }
#pragma unroll
        for (int i = 0; i < 4; i++) {       // B tile 32x128 from per-head weight layout
            int lin = tid + i * 256;
            int r = lin >> 5, c = (lin & 31) * 4;
            int n = n0 + c;
            int hh = n >> 6, kk = n & 63;
            *(float4*)&Bs[r][c] = tf32x4(*(const float4*)(W + ((size_t)hh * D + k0 + r) * 64 + kk));
        }
        __syncthreads();
#pragma unroll
        for (int ks = 0; ks < 4; ks++) {
            FragA a[4]; FragBr bb[2];
#pragma unroll
            for (int i = 0; i < 4; i++) wmma::load_matrix_sync(a[i], &As[wm * 64 + i * 16][ks * 8], 36);
#pragma unroll
            for (int j = 0; j < 2; j++) wmma::load_matrix_sync(bb[j], &Bs[ks * 8][wn * 32 + j * 16], 132);
#pragma unroll
            for (int i = 0; i < 4; i++)
#pragma unroll
                for (int j = 0; j < 2; j++) wmma::mma_sync(acc[i][j], a[i], bb[j], acc[i][j]);
        }
        __syncthreads();
    }
#pragma unroll
    for (int i = 0; i < 4; i++)
#pragma unroll
        for (int j = 0; j < 2; j++)
            wmma::store_matrix_sync(C + (size_t)(m0 + wm * 64 + i * 16) * 1024 + n0 + wn * 32 + j * 16,
                                    acc[i][j], 1024, wmma::mem_row_major);
}

// ---------------------------------------------------------------------------
// Kernel 2: fused attention. Per block: 32 q rows x full 1024 keys.
// scores -> softmax (warp-local) -> attn gmem write (once) -> PV -> g_ctx.
// grid (S/32, HB), block 512, dynamic smem 176.6 KB.
// ---------------------------------------------------------------------------
__global__ void __launch_bounds__(512, 1)
attn_kernel(float* __restrict__ attn)
{
    extern __shared__ float smem[];
    float* Sc = smem;                    // [QT][SC_LD]
    float* Kv = Sc + SMEM_SC;            // [CK][KV_LD]
    float* Qs = Kv + SMEM_KV;            // [QT][QS_LD]

    const int bh = blockIdx.y;
    const int b = bh / H, h = bh % H;
    const int q0 = blockIdx.x * QT;
    const int tid = threadIdx.x;
    const int warp = tid >> 5, lane = tid & 31;

    // ---- load Q tile (32x64), tf32-rounded ----
    {
        int r = tid >> 4, c = (tid & 15) * 4;
        *(float4*)&Qs[r * QS_LD + c] =
            tf32x4(*(const float4*)(g_q + ((size_t)(b * S + q0 + r)) * 1024 + h * 64 + c));
    }

    // ---- phase 1: scores = Q K^T / 32 into Sc ----
    const int qh = warp >> 3;            // 0..1 (16 q rows)
    const int kt = warp & 7;             // 0..7 (16 keys)
    for (int chunk = 0; chunk < S / CK; chunk++) {
        __syncthreads();
#pragma unroll
        for (int i = 0; i < 4; i++) {    // K chunk 128x64
            int lin = tid + i * 512;
            int r = lin >> 4, c = (lin & 15) * 4;
            *(float4*)&Kv[r * KV_LD + c] =
                tf32x4(*(const float4*)(g_k + ((size_t)(b * S + chunk * CK + r)) * 1024 + h * 64 + c));
        }
        __syncthreads();

        FragC acc; wmma::fill_fragment(acc, 0.0f);
#pragma unroll
        for (int ks = 0; ks < 8; ks++) {
            FragA a; FragBc bb;
            wmma::load_matrix_sync(a, &Qs[(qh * 16) * QS_LD + ks * 8], QS_LD);
            wmma::load_matrix_sync(bb, &Kv[(kt * 16) * KV_LD + ks * 8], KV_LD);
            wmma::mma_sync(acc, a, bb, acc);
        }
#pragma unroll
        for (int i = 0; i < acc.num_elements; i++) acc.x[i] *= INV_SCALE;
        wmma::store_matrix_sync(&Sc[(qh * 16) * SC_LD + chunk * CK + kt * 16], acc, SC_LD, wmma::mem_row_major);
    }
    __syncthreads();

    // ---- phase 2: softmax, warp-local (2 rows per warp), write attn once ----
    {
        float* arow_base = attn + ((size_t)(h * B + b) * S + q0) * S;
#pragma unroll
        for (int rr = 0; rr < 2; rr++) {
            const int row = warp * 2 + rr;
            float4 v[8];
#pragma unroll
            for (int i = 0; i < 8; i++) v[i] = *(float4*)&Sc[row * SC_LD + i * 128 + lane * 4];
            float m = -1e30f;
#pragma unroll
            for (int i = 0; i < 8; i++)
                m = fmaxf(m, fmaxf(fmaxf(v[i].x, v[i].y), fmaxf(v[i].z, v[i].w)));
#pragma unroll
            for (int o = 16; o; o >>= 1) m = fmaxf(m, __shfl_xor_sync(0xffffffffu, m, o));
            float s = 0.0f;
#pragma unroll
            for (int i = 0; i < 8; i++) {
                v[i].x = __expf(v[i].x - m); v[i].y = __expf(v[i].y - m);
                v[i].z = __expf(v[i].z - m); v[i].w = __expf(v[i].w - m);
                s += (v[i].x + v[i].y) + (v[i].z + v[i].w);
            }
#pragma unroll
            for (int o = 16; o; o >>= 1) s += __shfl_xor_sync(0xffffffffu, s, o);
            const float inv = 1.0f / s;
            float* grow = arow_base + (size_t)row * S;
#pragma unroll
            for (int i = 0; i < 8; i++) {
                float4 p; p.x = v[i].x * inv; p.y = v[i].y * inv; p.z = v[i].z * inv; p.w = v[i].w * inv;
                *(float4*)&grow[i * 128 + lane * 4] = p;                       // exact fp32 out
                *(float4*)&Sc[row * SC_LD + i * 128 + lane * 4] = tf32x4(p);   // tf32 for PV mma
            }
        }
    }

    // ---- phase 3: ctx = P V (split-k over 2 warp groups) ----
    const int kg = warp >> 3;            // 0..1
    const int t  = warp & 7;
    const int pqh = t >> 2;              // 0..1 (16 q rows)
    const int vn  = t & 3;               // 0..3 (16 v cols)
    FragC pacc; wmma::fill_fragment(pacc, 0.0f);

    for (int chunk = 0; chunk < S / CK; chunk++) {
        __syncthreads();
#pragma unroll
        for (int i = 0; i < 4; i++) {    // V chunk 128x64
            int lin = tid + i * 512;
            int r = lin >> 4, c = (lin & 15) * 4;
            *(float4*)&Kv[r * KV_LD + c] =
                tf32x4(*(const float4*)(g_v + ((size_t)(b * S + chunk * CK + r)) * 1024 + h * 64 + c));
        }
        __syncthreads();
#pragma unroll
        for (int i = 0; i < 8; i++) {
            int kk = kg * 64 + i * 8;
            FragA a; FragBr bb;
            wmma::load_matrix_sync(a, &Sc[(pqh * 16) * SC_LD + chunk * CK + kk], SC_LD);
            wmma::load_matrix_sync(bb, &Kv[kk * KV_LD + vn * 16], KV_LD);
            wmma::mma_sync(pacc, a, bb, pacc);
        }
    }
    __syncthreads();
    if (kg == 1)
        wmma::store_matrix_sync(&Qs[(pqh * 16) * QS_LD + vn * 16], pacc, QS_LD, wmma::mem_row_major);
    __syncthreads();
    if (kg == 0) {
        FragC other;
        wmma::load_matrix_sync(other, &Qs[(pqh * 16) * QS_LD + vn * 16], QS_LD, wmma::mem_row_major);
#pragma unroll
        for (int i = 0; i < pacc.num_elements; i++) pacc.x[i] += other.x[i];
        wmma::store_matrix_sync(g_ctx + ((size_t)(b * S + q0 + pqh * 16)) * 1024 + h * 64 + vn * 16,
                                pacc, 1024, wmma::mem_row_major);
    }
}

// ---------------------------------------------------------------------------
// Kernel 3: out = ctx @ w_proj^T   ([4096,1024] @ [1024,1024]^T)
// grid (32, 8), block 256. Block tile 128x128, warp tile 64x32.
// ---------------------------------------------------------------------------
__global__ void __launch_bounds__(256)
outproj_kernel(const float* __restrict__ wproj, float* __restrict__ out)
{
    const int m0 = blockIdx.x * 128;
    const int n0 = blockIdx.y * 128;

    __shared__ float As[128][36];
    __shared__ float Ws[128][36];        // [n_local][k_local]

    const int tid = threadIdx.x;
    const int warp = tid >> 5;
    const int wm = warp & 1, wn = warp >> 1;

    FragC acc[4][2];
#pragma unroll
    for (int i = 0; i < 4; i++) { wmma::fill_fragment(acc[i][0], 0.0f); wmma::fill_fragment(acc[i][1], 0.0f); }

    for (int k0 = 0; k0 < H * DV; k0 += 32) {
#pragma unroll
        for (int i = 0; i < 4; i++) {
            int lin = tid + i * 256;
            int r = lin >> 3, c = (lin & 7) * 4;
            *(float4*)&As[r][c] = tf32x4(*(const float4*)(g_ctx + (size_t)(m0 + r) * 1024 + k0 + c));
            *(float4*)&Ws[r][c] = tf32x4(*(const float4*)(wproj + (size_t)(n0 + r) * 1024 + k0 + c));
        }
        __syncthreads();
#pragma unroll
        for (int ks = 0; ks < 4; ks++) {
            FragA a[4]; FragBc bb[2];
#pragma unroll
            for (int i = 0; i < 4; i++) wmma::load_matrix_sync(a[i], &As[wm * 64 + i * 16][ks * 8], 36);
#pragma unroll
            for (int j = 0; j < 2; j++) wmma::load_matrix_sync(bb[j], &Ws[wn * 32 + j * 16][ks * 8], 36);
#pragma unroll
            for (int i = 0; i < 4; i++)
#pragma unroll
                for (int j = 0; j < 2; j++) wmma::mma_sync(acc[i][j], a[i], bb[j], acc[i][j]);
        }
        __syncthreads();
    }
#pragma unroll
    for (int i = 0; i < 4; i++)
#pragma unroll
        for (int j = 0; j < 2; j++)
            wmma::store_matrix_sync(out + (size_t)(m0 + wm * 64 + i * 16) * D + n0 + wn * 32 + j * 16,
                                    acc[i][j], D, wmma::mem_row_major);
}

// ---------------------------------------------------------------------------
// Kernel 4: out[i] += b_proj[i % D]
// ---------------------------------------------------------------------------
__global__ void __launch_bounds__(1024)
bias_kernel(float* __restrict__ out, const float* __restrict__ bias)
{
    size_t i = (size_t)blockIdx.x * 1024 + threadIdx.x;
    out[i] += bias[threadIdx.x];
}

// ---------------------------------------------------------------------------

extern "C" void kernel_launch(void* const* d_in, const int* in_sizes, int n_in,
                              void* d_out, int out_size)
{
    const float* query  = (const float*)d_in[0];
    const float* key    = (const float*)d_in[1];
    const float* value  = (const float*)d_in[2];
    const float* w_q    = (const float*)d_in[3];
    const float* w_k    = (const float*)d_in[4];
    const float* w_v    = (const float*)d_in[5];
    const float* w_proj = (const float*)d_in[6];
    const float* b_proj = (const float*)d_in[7];

    float* out  = (float*)d_out;            // [B, S, D]
    float* attn = out + OUT_ELEMS;          // [H*B, S, S]

    cudaFuncSetAttribute(attn_kernel, cudaFuncAttributeMaxDynamicSharedMemorySize,
                         (int)FUSED_SMEM_BYTES);

    proj_kernel<<<dim3(32, 8, 3), 256>>>(query, key, value, w_q, w_k, w_v);
    attn_kernel<<<dim3(S / QT, HB), 512, FUSED_SMEM_BYTES>>>(attn);
    outproj_kernel<<<dim3(32, 8), 256>>>(w_proj, out);
    bias_kernel<<<B * S, 1024>>>(out, b_proj);
}

// round 9
// speedup vs baseline: 1.3238x; 1.3238x over previous
#include <cuda_runtime.h>
#include <cstdint>
#include <mma.h>

using namespace nvcuda;

namespace {
constexpr int B  = 4;
constexpr int H  = 16;
constexpr int S  = 1024;
constexpr int D  = 1024;
constexpr int HB = H * B;
constexpr float INV_SCALE = 1.0f / 32.0f;        // 1/sqrt(D)
constexpr size_t OUT_ELEMS = (size_t)B * S * D;

constexpr int QT = 64;                 // q rows per attn block
constexpr int CK = 128;                // k/v chunk rows
constexpr int QS_LD = 68;
constexpr int KV_LD = 68;
constexpr int A3_LD = 132;
constexpr size_t ATTN_SMEM = (size_t)(QT * QS_LD + 2 * CK * KV_LD) * 4;   // 87040
constexpr size_t PROJ_SMEM = (size_t)2 * (128 * 36 + 32 * 132) * 4;       // 70656
constexpr size_t OPROJ_SMEM = (size_t)2 * (128 * 36 + 128 * 36) * 4;      // 73728
}

__device__ float g_q[(size_t)B * S * H * 64];    // [b*S+s][h*64+k]  (tf32-rounded)
__device__ float g_k[(size_t)B * S * H * 64];
__device__ float g_v[(size_t)B * S * H * 64];
__device__ float g_ctx[(size_t)B * S * H * 64];  // [b*S+q][h*64+v]  (tf32-rounded)

using FragA  = wmma::fragment<wmma::matrix_a, 16, 16, 8, wmma::precision::tf32, wmma::row_major>;
using FragBr = wmma::fragment<wmma::matrix_b, 16, 16, 8, wmma::precision::tf32, wmma::row_major>;
using FragBc = wmma::fragment<wmma::matrix_b, 16, 16, 8, wmma::precision::tf32, wmma::col_major>;
using FragC  = wmma::fragment<wmma::accumulator, 16, 16, 8, float>;

__device__ __forceinline__ void cp_async16(float* dst, const float* src) {
    unsigned int s = (unsigned int)__cvta_generic_to_shared(dst);
    asm volatile("cp.async.cg.shared.global [%0], [%1], 16;" :: "r"(s), "l"(src));
}
__device__ __forceinline__ void cp_commit() { asm volatile("cp.async.commit_group;"); }
template <int N> __device__ __forceinline__ void cp_wait() {
    asm volatile("cp.async.wait_group %0;" :: "n"(N));
}
template <typename F>
__device__ __forceinline__ void to_tf32(F& f) {
#pragma unroll
    for (int i = 0; i < f.num_elements; i++) f.x[i] = wmma::__float_to_tf32(f.x[i]);
}

// ---------------------------------------------------------------------------
// Kernel 1: QKV projections. C[m][h*64+k] = sum_d X[m][d] W[h][d][k]
// M=4096 N=1024 K=1024, grid (32,8,3), block 256, cp.async double-buffered.
// Epilogue stores tf32-rounded values.
// ---------------------------------------------------------------------------
__global__ void __launch_bounds__(256, 2)
proj_kernel(const float* __restrict__ xq, const float* __restrict__ xk,
            const float* __restrict__ xv, const float* __restrict__ wq,
            const float* __restrict__ wk, const float* __restrict__ wv)
{
    extern __shared__ float sm[];
    float* As = sm;                       // [2][128][36]
    float* Bs = sm + 2 * 128 * 36;        // [2][32][132]

    const int which = blockIdx.z;
    const float* A = (which == 0) ? xq : (which == 1) ? xk : xv;
    const float* W = (which == 0) ? wq : (which == 1) ? wk : wv;
    float* C       = (which == 0) ? g_q : (which == 1) ? g_k : g_v;

    const int m0 = blockIdx.x * 128;
    const int n0 = blockIdx.y * 128;
    const int tid = threadIdx.x;
    const int warp = tid >> 5;
    const int wm = warp & 1, wn = warp >> 1;

    auto prefetch = [&](int kt, int buf) {
        const int k0 = kt * 32;
        float* Ab = As + buf * 128 * 36;
        float* Bb = Bs + buf * 32 * 132;
#pragma unroll
        for (int i = 0; i < 4; i++) {
            int lin = tid + i * 256;
            int r = lin >> 3, c = (lin & 7) * 4;
            cp_async16(&Ab[r * 36 + c], A + (size_t)(m0 + r) * D + k0 + c);
        }
#pragma unroll
        for (int i = 0; i < 4; i++) {
            int lin = tid + i * 256;
            int r = lin >> 5, c = (lin & 31) * 4;
            int n = n0 + c;
            cp_async16(&Bb[r * 132 + c], W + ((size_t)(n >> 6) * D + k0 + r) * 64 + (n & 63));
        }
        cp_commit();
    };

    FragC acc[4][2];
#pragma unroll
    for (int i = 0; i < 4; i++) { wmma::fill_fragment(acc[i][0], 0.0f); wmma::fill_fragment(acc[i][1], 0.0f); }

    prefetch(0, 0);
    for (int kt = 0; kt < 32; kt++) {
        const int buf = kt & 1;
        if (kt < 31) { prefetch(kt + 1, buf ^ 1); cp_wait<1>(); } else { cp_wait<0>(); }
        __syncthreads();
        float* Ab = As + buf * 128 * 36;
        float* Bb = Bs + buf * 32 * 132;
#pragma unroll
        for (int ks = 0; ks < 4; ks++) {
            FragA a[4]; FragBr bb[2];
#pragma unroll
            for (int i = 0; i < 4; i++) { wmma::load_matrix_sync(a[i], &Ab[(wm * 64 + i * 16) * 36 + ks * 8], 36); to_tf32(a[i]); }
#pragma unroll
            for (int j = 0; j < 2; j++) { wmma::load_matrix_sync(bb[j], &Bb[(ks * 8) * 132 + wn * 32 + j * 16], 132); to_tf32(bb[j]); }
#pragma unroll
            for (int i = 0; i < 4; i++)
#pragma unroll
                for (int j = 0; j < 2; j++) wmma::mma_sync(acc[i][j], a[i], bb[j], acc[i][j]);
        }
        __syncthreads();
    }
#pragma unroll
    for (int i = 0; i < 4; i++)
#pragma unroll
        for (int j = 0; j < 2; j++) {
#pragma unroll
            for (int e = 0; e < acc[i][j].num_elements; e++)
                acc[i][j].x[e] = wmma::__float_to_tf32(acc[i][j].x[e]);
            wmma::store_matrix_sync(C + (size_t)(m0 + wm * 64 + i * 16) * 1024 + n0 + wn * 32 + j * 16,
                                    acc[i][j], 1024, wmma::mem_row_major);
        }
}

// ---------------------------------------------------------------------------
// Kernel 2: fused attention, 64 q rows per block, score strip lives in the
// attn gmem region (L2-resident). grid (16, HB), block 256, smem 87 KB.
// ---------------------------------------------------------------------------
__global__ void __launch_bounds__(256, 2)
attn_kernel(float* __restrict__ attn)
{
    extern __shared__ float sm[];
    float* Qs = sm;                    // [64][68]
    float* Kv = sm + QT * QS_LD;       // [2][128][68]  (phase 3 reuses as As3+Vs3)

    const int bh = blockIdx.y;
    const int b = bh / H, h = bh % H;
    const int q0 = blockIdx.x * QT;
    const int tid = threadIdx.x;
    const int warp = tid >> 5, lane = tid & 31;

    float* strip = attn + ((size_t)(h * B + b) * S + q0) * S;   // [64][1024]

    // ---- phase 1: scores = QK^T/32 -> strip ----
    {
#pragma unroll
        for (int i = 0; i < 4; i++) {    // Q tile 64x64 = 4096 floats
            int lin = tid + i * 256;
            int r = lin >> 4, c = (lin & 15) * 4;
            cp_async16(&Qs[r * QS_LD + c], g_q + ((size_t)(b * S + q0 + r)) * 1024 + h * 64 + c);
        }
        auto prefetchK = [&](int c, int buf) {
            float* Kb = Kv + buf * CK * KV_LD;
#pragma unroll
            for (int i = 0; i < 8; i++) {   // K chunk 128x64 = 8192 floats (FIXED: was i<4)
                int lin = tid + i * 256;
                int r = lin >> 4, cc = (lin & 15) * 4;
                cp_async16(&Kb[r * KV_LD + cc], g_k + ((size_t)(b * S + c * CK + r)) * 1024 + h * 64 + cc);
            }
            cp_commit();
        };
        prefetchK(0, 0);

        const int qh = warp >> 2;        // 0..1 -> 32 rows
        const int kw = warp & 3;         // 0..3 -> 32 cols (within chunk)

        for (int c = 0; c < S / CK; c++) {
            const int buf = c & 1;
            if (c < 7) { prefetchK(c + 1, buf ^ 1); cp_wait<1>(); } else { cp_wait<0>(); }
            __syncthreads();
            float* Kb = Kv + buf * CK * KV_LD;

            FragC acc[2][2];
#pragma unroll
            for (int i = 0; i < 2; i++) { wmma::fill_fragment(acc[i][0], 0.0f); wmma::fill_fragment(acc[i][1], 0.0f); }
#pragma unroll
            for (int ks = 0; ks < 8; ks++) {
                FragA a[2]; FragBc bb[2];
#pragma unroll
                for (int i = 0; i < 2; i++) wmma::load_matrix_sync(a[i], &Qs[(qh * 32 + i * 16) * QS_LD + ks * 8], QS_LD);
#pragma unroll
                for (int j = 0; j < 2; j++) wmma::load_matrix_sync(bb[j], &Kb[(kw * 32 + j * 16) * KV_LD + ks * 8], KV_LD);
#pragma unroll
                for (int i = 0; i < 2; i++)
#pragma unroll
                    for (int j = 0; j < 2; j++) wmma::mma_sync(acc[i][j], a[i], bb[j], acc[i][j]);
            }
#pragma unroll
            for (int i = 0; i < 2; i++)
#pragma unroll
                for (int j = 0; j < 2; j++) {
#pragma unroll
                    for (int e = 0; e < acc[i][j].num_elements; e++) acc[i][j].x[e] *= INV_SCALE;
                    wmma::store_matrix_sync(strip + (size_t)(qh * 32 + i * 16) * S + c * CK + kw * 32 + j * 16,
                                            acc[i][j], S, wmma::mem_row_major);
                }
            __syncthreads();
        }
    }

    // ---- phase 2: softmax in place (rows are L2-hot) ----
#pragma unroll
    for (int rr = 0; rr < 8; rr++) {
        const int row = warp * 8 + rr;
        float* p = strip + (size_t)row * S;
        float4 v[8];
#pragma unroll
        for (int i = 0; i < 8; i++) v[i] = *(float4*)&p[i * 128 + lane * 4];
        float m = -1e30f;
#pragma unroll
        for (int i = 0; i < 8; i++)
            m = fmaxf(m, fmaxf(fmaxf(v[i].x, v[i].y), fmaxf(v[i].z, v[i].w)));
#pragma unroll
        for (int o = 16; o; o >>= 1) m = fmaxf(m, __shfl_xor_sync(0xffffffffu, m, o));
        float s = 0.0f;
#pragma unroll
        for (int i = 0; i < 8; i++) {
            v[i].x = __expf(v[i].x - m); v[i].y = __expf(v[i].y - m);
            v[i].z = __expf(v[i].z - m); v[i].w = __expf(v[i].w - m);
            s += (v[i].x + v[i].y) + (v[i].z + v[i].w);
        }
#pragma unroll
        for (int o = 16; o; o >>= 1) s += __shfl_xor_sync(0xffffffffu, s, o);
        const float inv = 1.0f / s;
#pragma unroll
        for (int i = 0; i < 8; i++) {
            float4 q; q.x = v[i].x * inv; q.y = v[i].y * inv; q.z = v[i].z * inv; q.w = v[i].w * inv;
            *(float4*)&p[i * 128 + lane * 4] = q;
        }
    }
    __syncthreads();

    // ---- phase 3: ctx = P V  (split-k over 2 warp groups) ----
    {
        float* As3 = Kv;                   // [64][132]
        float* Vs3 = Kv + QT * A3_LD;      // [128][68]

        const int kg = warp >> 2;          // 0..1 -> k half of each chunk
        const int qh = (warp >> 1) & 1;    // 0..1 -> 32 rows
        const int vn = warp & 1;           // 0..1 -> 32 cols

        FragC pacc[2][2];
#pragma unroll
        for (int i = 0; i < 2; i++) { wmma::fill_fragment(pacc[i][0], 0.0f); wmma::fill_fragment(pacc[i][1], 0.0f); }

        for (int c = 0; c < S / CK; c++) {
#pragma unroll
            for (int i = 0; i < 8; i++) {          // P chunk 64x128 (L2-hot)
                int lin = tid + i * 256;
                int r = lin >> 5, cc = (lin & 31) * 4;
                cp_async16(&As3[r * A3_LD + cc], strip + (size_t)r * S + c * CK + cc);
            }
#pragma unroll
            for (int i = 0; i < 8; i++) {          // V chunk 128x64
                int lin = tid + i * 256;
                int r = lin >> 4, cc = (lin & 15) * 4;
                cp_async16(&Vs3[r * KV_LD + cc], g_v + ((size_t)(b * S + c * CK + r)) * 1024 + h * 64 + cc);
            }
            cp_commit();
            cp_wait<0>();
            __syncthreads();
#pragma unroll
            for (int ks = 0; ks < 8; ks++) {
                const int kk = kg * 64 + ks * 8;
                FragA a[2]; FragBr bb[2];
#pragma unroll
                for (int i = 0; i < 2; i++) { wmma::load_matrix_sync(a[i], &As3[(qh * 32 + i * 16) * A3_LD + kk], A3_LD); to_tf32(a[i]); }
#pragma unroll
                for (int j = 0; j < 2; j++) wmma::load_matrix_sync(bb[j], &Vs3[kk * KV_LD + vn * 32 + j * 16], KV_LD);
#pragma unroll
                for (int i = 0; i < 2; i++)
#pragma unroll
                    for (int j = 0; j < 2; j++) wmma::mma_sync(pacc[i][j], a[i], bb[j], pacc[i][j]);
            }
            __syncthreads();
        }

        // cross-k reduction via Qs region (64x64, ld 68)
        if (kg == 1) {
#pragma unroll
            for (int i = 0; i < 2; i++)
#pragma unroll
                for (int j = 0; j < 2; j++)
                    wmma::store_matrix_sync(&Qs[(qh * 32 + i * 16) * QS_LD + vn * 32 + j * 16],
                                            pacc[i][j], QS_LD, wmma::mem_row_major);
        }
        __syncthreads();
        if (kg == 0) {
#pragma unroll
            for (int i = 0; i < 2; i++)
#pragma unroll
                for (int j = 0; j < 2; j++) {
                    FragC other;
                    wmma::load_matrix_sync(other, &Qs[(qh * 32 + i * 16) * QS_LD + vn * 32 + j * 16],
                                           QS_LD, wmma::mem_row_major);
#pragma unroll
                    for (int e = 0; e < pacc[i][j].num_elements; e++)
                        pacc[i][j].x[e] = wmma::__float_to_tf32(pacc[i][j].x[e] + other.x[e]);
                    wmma::store_matrix_sync(g_ctx + ((size_t)(b * S + q0 + qh * 32 + i * 16)) * 1024 + h * 64 + vn * 32 + j * 16,
                                            pacc[i][j], 1024, wmma::mem_row_major);
                }
        }
    }
}

// ---------------------------------------------------------------------------
// Kernel 3: out = ctx @ w_proj^T, grid (32,8), block 256, cp.async pipelined.
// ---------------------------------------------------------------------------
__global__ void __launch_bounds__(256, 2)
outproj_kernel(const float* __restrict__ wproj, float* __restrict__ out)
{
    extern __shared__ float sm[];
    float* As = sm;                       // [2][128][36]
    float* Ws = sm + 2 * 128 * 36;        // [2][128][36]

    const int m0 = blockIdx.x * 128;
    const int n0 = blockIdx.y * 128;
    const int tid = threadIdx.x;
    const int warp = tid >> 5;
    const int wm = warp & 1, wn = warp >> 1;

    auto prefetch = [&](int kt, int buf) {
        const int k0 = kt * 32;
        float* Ab = As + buf * 128 * 36;
        float* Wb = Ws + buf * 128 * 36;
#pragma unroll
        for (int i = 0; i < 4; i++) {
            int lin = tid + i * 256;
            int r = lin >> 3, c = (lin & 7) * 4;
            cp_async16(&Ab[r * 36 + c], g_ctx + (size_t)(m0 + r) * 1024 + k0 + c);
            cp_async16(&Wb[r * 36 + c], wproj + (size_t)(n0 + r) * 1024 + k0 + c);
        }
        cp_commit();
    };

    FragC acc[4][2];
#pragma unroll
    for (int i = 0; i < 4; i++) { wmma::fill_fragment(acc[i][0], 0.0f); wmma::fill_fragment(acc[i][1], 0.0f); }

    prefetch(0, 0);
    for (int kt = 0; kt < 32; kt++) {
        const int buf = kt & 1;
        if (kt < 31) { prefetch(kt + 1, buf ^ 1); cp_wait<1>(); } else { cp_wait<0>(); }
        __syncthreads();
        float* Ab = As + buf * 128 * 36;
        float* Wb = Ws + buf * 128 * 36;
#pragma unroll
        for (int ks = 0; ks < 4; ks++) {
            FragA a[4]; FragBc bb[2];
#pragma unroll
            for (int i = 0; i < 4; i++) wmma::load_matrix_sync(a[i], &Ab[(wm * 64 + i * 16) * 36 + ks * 8], 36);
#pragma unroll
            for (int j = 0; j < 2; j++) { wmma::load_matrix_sync(bb[j], &Wb[(wn * 32 + j * 16) * 36 + ks * 8], 36); to_tf32(bb[j]); }
#pragma unroll
            for (int i = 0; i < 4; i++)
#pragma unroll
                for (int j = 0; j < 2; j++) wmma::mma_sync(acc[i][j], a[i], bb[j], acc[i][j]);
        }
        __syncthreads();
    }
#pragma unroll
    for (int i = 0; i < 4; i++)
#pragma unroll
        for (int j = 0; j < 2; j++)
            wmma::store_matrix_sync(out + (size_t)(m0 + wm * 64 + i * 16) * D + n0 + wn * 32 + j * 16,
                                    acc[i][j], D, wmma::mem_row_major);
}

// ---------------------------------------------------------------------------
// Kernel 4: out[i] += b_proj[i % D]
// ---------------------------------------------------------------------------
__global__ void __launch_bounds__(1024)
bias_kernel(float* __restrict__ out, const float* __restrict__ bias)
{
    size_t i = (size_t)blockIdx.x * 1024 + threadIdx.x;
    out[i] += bias[threadIdx.x];
}

// ---------------------------------------------------------------------------

extern "C" void kernel_launch(void* const* d_in, const int* in_sizes, int n_in,
                              void* d_out, int out_size)
{
    const float* query  = (const float*)d_in[0];
    const float* key    = (const float*)d_in[1];
    const float* value  = (const float*)d_in[2];
    const float* w_q    = (const float*)d_in[3];
    const float* w_k    = (const float*)d_in[4];
    const float* w_v    = (const float*)d_in[5];
    const float* w_proj = (const float*)d_in[6];
    const float* b_proj = (const float*)d_in[7];

    float* out  = (float*)d_out;            // [B, S, D]
    float* attn = out + OUT_ELEMS;          // [H*B, S, S]

    cudaFuncSetAttribute(proj_kernel, cudaFuncAttributeMaxDynamicSharedMemorySize, (int)PROJ_SMEM);
    cudaFuncSetAttribute(attn_kernel, cudaFuncAttributeMaxDynamicSharedMemorySize, (int)ATTN_SMEM);
    cudaFuncSetAttribute(outproj_kernel, cudaFuncAttributeMaxDynamicSharedMemorySize, (int)OPROJ_SMEM);

    proj_kernel<<<dim3(32, 8, 3), 256, PROJ_SMEM>>>(query, key, value, w_q, w_k, w_v);
    attn_kernel<<<dim3(S / QT, HB), 256, ATTN_SMEM>>>(attn);
    outproj_kernel<<<dim3(32, 8), 256, OPROJ_SMEM>>>(w_proj, out);
    bias_kernel<<<B * S, 1024>>>(out, b_proj);
}